// round 7
// baseline (speedup 1.0000x reference)
#include <cuda_runtime.h>
#include <cuda_bf16.h>

// ---------------------------------------------------------------------------
// MLP_TI_Gram fully fused: FFT-corr (Wiener-Khinchin) -> gemm1 -> mlp23
// in ONE kernel, phases chained by device-side monotonic flags.
// 128 CTAs x 512 thr, 1 CTA/SM, all co-resident (grid <= 148 SMs).
// ---------------------------------------------------------------------------

#define BATCH 128
#define NSEQ  1024
#define HID   128

typedef unsigned long long u64;

__device__ float    g_c[BATCH * NSEQ];     // correlation (scratch)
__device__ float    g_h1[BATCH * HID];     // layer-1 activations (scratch)
__device__ unsigned g_flag1[BATCH];        // per-batch fft-done (monotonic)
__device__ unsigned g_flag2[16];           // per-btile h1-done (monotonic, +8/call)

// ---- dynamic smem layout (bytes) ------------------------------------------
#define OFF_BUFA 0                         // float2[2][1024]  16384
#define OFF_BUFB 16384                     // float2[2][1024]  16384
#define OFF_TW   32768                     // float2[512]       4096
#define OFF_W1D  36864                     // u64[1024][16]   131072
#define OFF_RED  167936                    // u64[32][66]      16896
#define SMEM_BYTES 184832
#define CSH_OFF  0                         // u64[4][1025]     32800 (overlays fft bufs)
#define CSH_PITCH 1025
#define RED_PITCH 66

// ---- f32x2 packed helpers (Blackwell, PTX-only) ---------------------------
__device__ __forceinline__ u64 pk2(float lo, float hi) {
    u64 r;
    asm("mov.b64 %0, {%1,%2};" : "=l"(r) : "f"(lo), "f"(hi));
    return r;
}
__device__ __forceinline__ void upk2(u64 v, float& lo, float& hi) {
    asm("mov.b64 {%0,%1}, %2;" : "=f"(lo), "=f"(hi) : "l"(v));
}
__device__ __forceinline__ u64 fma2(u64 a, u64 b, u64 c) {
    u64 d;
    asm("fma.rn.f32x2 %0, %1, %2, %3;" : "=l"(d) : "l"(a), "l"(b), "l"(c));
    return d;
}
__device__ __forceinline__ u64 add2(u64 a, u64 b) {
    u64 d;
    asm("add.rn.f32x2 %0, %1, %2;" : "=l"(d) : "l"(a), "l"(b));
    return d;
}

__device__ __forceinline__ float celu1(float v) {
    return v > 0.0f ? v : expm1f(v);
}
__device__ __forceinline__ float2 cmul(float2 a, float2 b) {
    return make_float2(a.x * b.x - a.y * b.y, a.x * b.y + a.y * b.x);
}
__device__ __forceinline__ unsigned ldacq(const unsigned* p) {
    unsigned v;
    asm volatile("ld.acquire.gpu.u32 %0, [%1];" : "=r"(v) : "l"(p));
    return v;
}

// ---------------------------------------------------------------------------
__global__ __launch_bounds__(512, 1)
void fused_kernel(const float* __restrict__ x,
                  const float* __restrict__ W1, const float* __restrict__ b1,
                  const float* __restrict__ W2, const float* __restrict__ b2,
                  const float* __restrict__ W3, const float* __restrict__ b3,
                  float* __restrict__ out) {
    extern __shared__ char dsm[];
    const int B = blockIdx.x;
    const int t = threadIdx.x;

    __shared__ unsigned tgt1_s, tgt2_s;

    // L2 prefetch of weight slices this block will need later (overlaps FFT)
    {
        const int H0p = (B & 7) * 16;
        for (int j = t; j < 1024; j += 512)
            asm volatile("prefetch.global.L2 [%0];" :: "l"(W1 + j * HID + H0p));
        if (t < 4)
            asm volatile("prefetch.global.L2 [%0];"
                         :: "l"((const char*)W2 + ((size_t)B * 4 + t) * 128));
    }

    // ======================= phase 1: FFT correlation =======================
    {
        float2 (*bufA)[1024] = (float2(*)[1024])(dsm + OFF_BUFA);
        float2 (*bufB)[1024] = (float2(*)[1024])(dsm + OFF_BUFB);
        float2* tw = (float2*)(dsm + OFF_TW);

        // twiddle: tw[m] = exp(-2*pi*i*m/1024)
        {
            float s_, c_;
            sincospif(-(float)t * (1.0f / 512.0f), &s_, &c_);
            tw[t] = make_float2(c_, s_);
        }
        bufA[1][t].y = 0.0f;
        bufA[1][t + 512].y = 0.0f;

        // load x[B]: 3072 floats = 768 float4, scatter to (j, d)
        {
            const float4* __restrict__ xv =
                (const float4*)(x + (size_t)B * NSEQ * 3);
            for (int i = t; i < 768; i += 512) {
                float4 v = xv[i];
                float vals[4] = {v.x, v.y, v.z, v.w};
                int e = 4 * i;
#pragma unroll
                for (int k = 0; k < 4; k++) {
                    int ee = e + k;
                    int j = ee / 3;
                    int d = ee - 3 * j;
                    if (d == 0)      bufA[0][j].x = vals[k];
                    else if (d == 1) bufA[0][j].y = vals[k];
                    else             bufA[1][j].x = vals[k];
                }
            }
        }
        __syncthreads();

        const int f = t >> 8;     // signal (0: ch0+i*ch1, 1: ch2)
        const int i = t & 255;

        // forward: 5 radix-4 stages, 2 signals
        {
            float2 (*src)[1024] = bufA;
            float2 (*dst)[1024] = bufB;
#pragma unroll
            for (int s = 0; s < 5; s++) {
                const int L = 1 << (2 * s);
                const int q = i & (L - 1);
                const int d = ((i >> (2 * s)) << (2 * s + 2)) | q;
                const float2 w1t = tw[q << (8 - 2 * s)];
                const float2 w2t = make_float2(w1t.x * w1t.x - w1t.y * w1t.y,
                                               2.0f * w1t.x * w1t.y);
                const float2 w3t = cmul(w2t, w1t);

                float2 a0 = src[f][i];
                float2 a1 = src[f][i + 256];
                float2 a2 = src[f][i + 512];
                float2 a3 = src[f][i + 768];
                float2 bb1 = cmul(a1, w1t);
                float2 bb2 = cmul(a2, w2t);
                float2 bb3 = cmul(a3, w3t);

                float2 t02p = make_float2(a0.x + bb2.x, a0.y + bb2.y);
                float2 t02m = make_float2(a0.x - bb2.x, a0.y - bb2.y);
                float2 t13p = make_float2(bb1.x + bb3.x, bb1.y + bb3.y);
                float2 t13m = make_float2(bb1.x - bb3.x, bb1.y - bb3.y);

                dst[f][d]         = make_float2(t02p.x + t13p.x, t02p.y + t13p.y);
                dst[f][d + L]     = make_float2(t02m.x + t13m.y, t02m.y - t13m.x);
                dst[f][d + 2 * L] = make_float2(t02p.x - t13p.x, t02p.y - t13p.y);
                dst[f][d + 3 * L] = make_float2(t02m.x - t13m.y, t02m.y + t13m.x);

                float2 (*tmp)[1024] = src; src = dst; dst = tmp;
                __syncthreads();
            }
        }  // spectra in bufB

        // power spectrum: P + 0i into bufA[0]
#pragma unroll
        for (int it = 0; it < 2; it++) {
            int k = t + it * 512;
            int m = (1024 - k) & 1023;
            float2 z  = bufB[0][k];
            float2 zm = bufB[0][m];
            float2 z2 = bufB[1][k];
            float P = 0.5f * (z.x * z.x + z.y * z.y + zm.x * zm.x + zm.y * zm.y)
                    + (z2.x * z2.x + z2.y * z2.y);
            bufA[0][k] = make_float2(P, 0.0f);
        }
        __syncthreads();

        // inverse (== forward on real-even P): 5 stages, 1 signal
        {
            float2 (*src)[1024] = bufA;
            float2 (*dst)[1024] = bufB;
#pragma unroll
            for (int s = 0; s < 5; s++) {
                if (t < 256) {
                    const int L = 1 << (2 * s);
                    const int q = t & (L - 1);
                    const int d = ((t >> (2 * s)) << (2 * s + 2)) | q;
                    const float2 w1t = tw[q << (8 - 2 * s)];
                    const float2 w2t = make_float2(w1t.x * w1t.x - w1t.y * w1t.y,
                                                   2.0f * w1t.x * w1t.y);
                    const float2 w3t = cmul(w2t, w1t);

                    float2 a0 = src[0][t];
                    float2 a1 = src[0][t + 256];
                    float2 a2 = src[0][t + 512];
                    float2 a3 = src[0][t + 768];
                    float2 bb1 = cmul(a1, w1t);
                    float2 bb2 = cmul(a2, w2t);
                    float2 bb3 = cmul(a3, w3t);

                    float2 t02p = make_float2(a0.x + bb2.x, a0.y + bb2.y);
                    float2 t02m = make_float2(a0.x - bb2.x, a0.y - bb2.y);
                    float2 t13p = make_float2(bb1.x + bb3.x, bb1.y + bb3.y);
                    float2 t13m = make_float2(bb1.x - bb3.x, bb1.y - bb3.y);

                    dst[0][d]         = make_float2(t02p.x + t13p.x, t02p.y + t13p.y);
                    dst[0][d + L]     = make_float2(t02m.x + t13m.y, t02m.y - t13m.x);
                    dst[0][d + 2 * L] = make_float2(t02p.x - t13p.x, t02p.y - t13p.y);
                    dst[0][d + 3 * L] = make_float2(t02m.x - t13m.y, t02m.y + t13m.x);
                }
                float2 (*tmp)[1024] = src; src = dst; dst = tmp;
                __syncthreads();
            }
        }  // result in bufB[0]

        const float inv = 1.0f / (1024.0f * 1024.0f);
        g_c[(size_t)B * NSEQ + t]       = bufB[0][t].x * inv;
        g_c[(size_t)B * NSEQ + t + 512] = bufB[0][t + 512].x * inv;
    }

    // release: this batch's c is ready
    __threadfence();
    __syncthreads();
    if (t == 0) tgt1_s = atomicAdd(&g_flag1[B], 1) + 1;
    __syncthreads();
    const unsigned tgt1 = tgt1_s;

    // ======================= phase 2: gemm1 tile ============================
    const int bt = B >> 3;
    const int ht = B & 7;
    const int b0 = bt * 8;
    const int H0 = ht * 16;

    if (t < 8) {  // acquire: wait for the 8 producer batches
        const unsigned* fl = &g_flag1[b0 + t];
        while ((int)(ldacq(fl) - tgt1) < 0) { }
    }
    __syncthreads();
    __threadfence();

    {
        u64 (*csh)[CSH_PITCH] = (u64(*)[CSH_PITCH])(dsm + CSH_OFF);
        u64 (*w1d)[16]        = (u64(*)[16])(dsm + OFF_W1D);
        u64 (*red)[RED_PITCH] = (u64(*)[RED_PITCH])(dsm + OFF_RED);

#pragma unroll
        for (int it = 0; it < 8; it++) {
            int idx = t + it * 512;
            int bp_ = idx >> 10, j = idx & 1023;
            csh[bp_][j] = pk2(g_c[(b0 + 2 * bp_) * NSEQ + j],
                              g_c[(b0 + 2 * bp_ + 1) * NSEQ + j]);
        }
#pragma unroll
        for (int it = 0; it < 8; it++) {
            int idx = t + it * 512;
            int j = idx >> 2, hq = idx & 3;
            float4 wv = *(const float4*)&W1[j * HID + H0 + hq * 4];
            ulonglong2* dst = (ulonglong2*)&w1d[j][hq * 4];
            dst[0] = make_ulonglong2(pk2(wv.x, wv.x), pk2(wv.y, wv.y));
            dst[1] = make_ulonglong2(pk2(wv.z, wv.z), pk2(wv.w, wv.w));
        }
        __syncthreads();

        const int bp = t & 3;
        const int h4 = (t >> 2) & 3;
        const int jq = t >> 4;
        const int j0 = jq * 32;

        u64 a0 = 0ull, a1 = 0ull, a2 = 0ull, a3 = 0ull;
#pragma unroll 8
        for (int j = j0; j < j0 + 32; j++) {
            u64 cv = csh[bp][j];
            const ulonglong2* wr = (const ulonglong2*)&w1d[j][h4 * 4];
            ulonglong2 w01 = wr[0];
            ulonglong2 w23 = wr[1];
            a0 = fma2(cv, w01.x, a0);
            a1 = fma2(cv, w01.y, a1);
            a2 = fma2(cv, w23.x, a2);
            a3 = fma2(cv, w23.y, a3);
        }
        {
            ulonglong2* rr = (ulonglong2*)&red[jq][bp * 16 + h4 * 4];
            rr[0] = make_ulonglong2(a0, a1);
            rr[1] = make_ulonglong2(a2, a3);
        }
        __syncthreads();

        if (t < 64) {
            int bp_ = t >> 4, h = t & 15;
            int cell = bp_ * 16 + h;
            u64 s0 = 0ull, s1 = 0ull, s2 = 0ull, s3 = 0ull;
#pragma unroll
            for (int q = 0; q < 32; q += 4) {
                s0 = add2(s0, red[q + 0][cell]);
                s1 = add2(s1, red[q + 1][cell]);
                s2 = add2(s2, red[q + 2][cell]);
                s3 = add2(s3, red[q + 3][cell]);
            }
            u64 s = add2(add2(s0, s1), add2(s2, s3));
            float va, vb;
            upk2(s, va, vb);
            float bb = b1[H0 + h];
            g_h1[(b0 + 2 * bp_) * HID + H0 + h]     = celu1(va + bb);
            g_h1[(b0 + 2 * bp_ + 1) * HID + H0 + h] = celu1(vb + bb);
        }
    }

    // release: this (bt,ht) tile of h1 is ready
    __threadfence();
    __syncthreads();
    if (t == 0) {
        unsigned old = atomicAdd(&g_flag2[bt], 1);
        tgt2_s = (old & ~7u) + 8u;       // epoch base + all 8 tiles
    }
    __syncthreads();
    const unsigned tgt2 = tgt2_s;

    // ======================= phase 3: mlp23 for batch B =====================
    if (t == 0) {
        const unsigned* fl = &g_flag2[bt];
        while ((int)(ldacq(fl) - tgt2) < 0) { }
    }
    __syncthreads();
    __threadfence();

    {
        float* h1s = (float*)dsm;              // 128 floats
        float* s2  = (float*)(dsm + 512);      // 4*128 floats

        if (t < HID) h1s[t] = g_h1[(size_t)B * HID + t];
        __syncthreads();

        const int kh = t >> 7;                 // 0..3
        const int h  = t & 127;
        const int k0 = kh * 32;
        float acc0 = 0.f, acc1 = 0.f, acc2 = 0.f, acc3 = 0.f;
#pragma unroll
        for (int k = k0; k < k0 + 32; k += 4) {
            acc0 += h1s[k + 0] * W2[(k + 0) * HID + h];
            acc1 += h1s[k + 1] * W2[(k + 1) * HID + h];
            acc2 += h1s[k + 2] * W2[(k + 2) * HID + h];
            acc3 += h1s[k + 3] * W2[(k + 3) * HID + h];
        }
        s2[kh * 128 + h] = (acc0 + acc1) + (acc2 + acc3);
        __syncthreads();

        if (t < HID) {
            float v = s2[h] + s2[128 + h] + s2[256 + h] + s2[384 + h] + b2[h];
            h1s[h] = celu1(v) * W3[h];
        }
        __syncthreads();
#pragma unroll
        for (int o = 64; o > 0; o >>= 1) {
            if (t < o) h1s[t] += h1s[t + o];
            __syncthreads();
        }
        if (t == 0) out[B] = h1s[0] + b3[0];
    }
}

// ---------------------------------------------------------------------------
extern "C" void kernel_launch(void* const* d_in, const int* in_sizes, int n_in,
                              void* d_out, int out_size) {
    const float* x  = (const float*)d_in[0];
    const float* W1 = (const float*)d_in[1];
    const float* b1 = (const float*)d_in[2];
    const float* W2 = (const float*)d_in[3];
    const float* b2 = (const float*)d_in[4];
    const float* W3 = (const float*)d_in[5];
    const float* b3 = (const float*)d_in[6];
    float* out = (float*)d_out;

    static int configured = 0;
    if (!configured) {
        cudaFuncSetAttribute(fused_kernel,
                             cudaFuncAttributeMaxDynamicSharedMemorySize,
                             SMEM_BYTES);
        configured = 1;
    }

    fused_kernel<<<BATCH, 512, SMEM_BYTES>>>(x, W1, b1, W2, b2, W3, b3, out);
}